// round 6
// baseline (speedup 1.0000x reference)
#include <cuda_runtime.h>
#include <cuda_bf16.h>

// BCELoss(reduce=False) with "correct-side" masking.
//   y in {0,1}. q = y ? p : 1-p.  loss = (q > 0.5) ? 0 : -max(log q, -100)
// log(1-p) only evaluated when p >= 0.5 -> 1-p exact (Sterbenz), matches
// reference log1p(-p) to fp32 precision.
//
// Round 5: persistent single-wave grid (152 SMs x 4 CTAs = 608 blocks of
// 512 threads), grid-stride loop with 2 float4 per input per iteration
// (4 front-batched LDG.128 -> MLP=4). Eliminates ~6 wave transitions and
// tail-wave imbalance of the R4 4096-CTA launch.

__device__ __forceinline__ float bce_elem(float p, float y) {
    float q = (y > 0.5f) ? p : (1.0f - p);
    if (q > 0.5f) return 0.0f;
    return -fmaxf(__logf(q), -100.0f);
}

__device__ __forceinline__ float4 bce_vec4(float4 p, float4 y) {
    float4 o;
    o.x = bce_elem(p.x, y.x);
    o.y = bce_elem(p.y, y.y);
    o.z = bce_elem(p.z, y.z);
    o.w = bce_elem(p.w, y.w);
    return o;
}

__global__ void __launch_bounds__(512)
neo_loss_persist(const float4* __restrict__ pred,
                 const float4* __restrict__ actual,
                 float4* __restrict__ out,
                 int n4) {
    const int stride = gridDim.x * blockDim.x;       // threads in grid
    int i = blockIdx.x * blockDim.x + threadIdx.x;

    // main loop: 2 float4 slots per input per iteration, loads front-batched
    for (; i + stride < n4; i += 2 * stride) {
        int j = i + stride;
        float4 p0 = pred[i];
        float4 p1 = pred[j];
        float4 y0 = actual[i];
        float4 y1 = actual[j];
        out[i] = bce_vec4(p0, y0);
        out[j] = bce_vec4(p1, y1);
    }
    // at most one slot left per thread
    if (i < n4) {
        float4 p0 = pred[i];
        float4 y0 = actual[i];
        out[i] = bce_vec4(p0, y0);
    }
}

__global__ void neo_loss_tail(const float* __restrict__ pred,
                              const float* __restrict__ actual,
                              float* __restrict__ out,
                              int start, int n) {
    int i = start + blockIdx.x * blockDim.x + threadIdx.x;
    if (i >= n) return;
    out[i] = bce_elem(pred[i], actual[i]);
}

extern "C" void kernel_launch(void* const* d_in, const int* in_sizes, int n_in,
                              void* d_out, int out_size) {
    const float* pred   = (const float*)d_in[0];
    const float* actual = (const float*)d_in[1];
    float* out = (float*)d_out;
    int n = in_sizes[0];

    int n4 = n >> 2;            // float4 count
    int vec_elems = n4 << 2;

    if (n4 > 0) {
        // one full wave on GB300: 152 SMs x 4 CTAs (512 thr, 2048 thr/SM)
        int blocks = 152 * 4;
        int max_useful = (n4 + 511) / 512;   // never launch more than work
        if (blocks > max_useful) blocks = max_useful;
        neo_loss_persist<<<blocks, 512>>>(
            (const float4*)pred, (const float4*)actual, (float4*)out, n4);
    }
    if (vec_elems < n) {
        int rem = n - vec_elems;
        neo_loss_tail<<<(rem + 255) / 256, 256>>>(pred, actual, out, vec_elems, n);
    }
}

// round 7
// speedup vs baseline: 1.0462x; 1.0462x over previous
#include <cuda_runtime.h>
#include <cuda_bf16.h>

// BCELoss(reduce=False) with "correct-side" masking.
//   y in {0,1}. q = y ? p : 1-p.  loss = (q > 0.5) ? 0 : -max(log q, -100)
// log(1-p) only evaluated when p >= 0.5 -> 1-p exact (Sterbenz), matches
// reference log1p(-p) to fp32 precision.
//
// Round 6: revert to R4's contiguous flat partition (best locality:
// DRAM 77.8% vs 73.6% for the strided persistent variant), and double
// per-thread ILP: each 512-thread CTA covers 2048 contiguous float4 slots,
// 4 slots/thread at +0/+512/+1024/+1536 -> 8 front-batched LDG.128.

__device__ __forceinline__ float bce_elem(float p, float y) {
    float q = (y > 0.5f) ? p : (1.0f - p);
    if (q > 0.5f) return 0.0f;
    return -fmaxf(__logf(q), -100.0f);
}

__device__ __forceinline__ float4 bce_vec4(float4 p, float4 y) {
    float4 o;
    o.x = bce_elem(p.x, y.x);
    o.y = bce_elem(p.y, y.y);
    o.z = bce_elem(p.z, y.z);
    o.w = bce_elem(p.w, y.w);
    return o;
}

__global__ void __launch_bounds__(512)
neo_loss_vec16(const float4* __restrict__ pred,
               const float4* __restrict__ actual,
               float4* __restrict__ out,
               int n4) {
    int base = blockIdx.x * 2048 + threadIdx.x;

    if (base + 1536 < n4) {
        // full fast path: 8 front-batched LDG.128 (MLP=8)
        float4 p0 = pred[base];
        float4 p1 = pred[base + 512];
        float4 p2 = pred[base + 1024];
        float4 p3 = pred[base + 1536];
        float4 y0 = actual[base];
        float4 y1 = actual[base + 512];
        float4 y2 = actual[base + 1024];
        float4 y3 = actual[base + 1536];
        out[base]        = bce_vec4(p0, y0);
        out[base + 512]  = bce_vec4(p1, y1);
        out[base + 1024] = bce_vec4(p2, y2);
        out[base + 1536] = bce_vec4(p3, y3);
    } else {
        #pragma unroll
        for (int s = 0; s < 4; s++) {
            int i = base + s * 512;
            if (i < n4) {
                float4 p = pred[i];
                float4 y = actual[i];
                out[i] = bce_vec4(p, y);
            }
        }
    }
}

__global__ void neo_loss_tail(const float* __restrict__ pred,
                              const float* __restrict__ actual,
                              float* __restrict__ out,
                              int start, int n) {
    int i = start + blockIdx.x * blockDim.x + threadIdx.x;
    if (i >= n) return;
    out[i] = bce_elem(pred[i], actual[i]);
}

extern "C" void kernel_launch(void* const* d_in, const int* in_sizes, int n_in,
                              void* d_out, int out_size) {
    const float* pred   = (const float*)d_in[0];
    const float* actual = (const float*)d_in[1];
    float* out = (float*)d_out;
    int n = in_sizes[0];

    int n4 = n >> 2;            // float4 count
    int vec_elems = n4 << 2;

    if (n4 > 0) {
        // 2048 float4 slots per block (4 per thread, 512 threads)
        int blocks = (n4 + 2047) / 2048;
        neo_loss_vec16<<<blocks, 512>>>(
            (const float4*)pred, (const float4*)actual, (float4*)out, n4);
    }
    if (vec_elems < n) {
        int rem = n - vec_elems;
        neo_loss_tail<<<(rem + 255) / 256, 256>>>(pred, actual, out, vec_elems, n);
    }
}